// round 7
// baseline (speedup 1.0000x reference)
#include <cuda_runtime.h>
#include <math.h>

#define NN 1024
#define H 128
#define THREADS 1024    // main kernel
#define PTHREADS 256    // prep kernel
#define PROWS 4         // rows per prep block

typedef unsigned long long u64;
#define ABSM 0x7FFFFFFF7FFFFFFFULL

// ---------------- f32x2 packed helpers ----------------
__device__ __forceinline__ u64 f2add(u64 a, u64 b) {
    u64 r; asm("add.rn.f32x2 %0,%1,%2;" : "=l"(r) : "l"(a), "l"(b)); return r;
}
__device__ __forceinline__ void f2fma(u64& d, u64 a, u64 b) {
    asm("fma.rn.f32x2 %0,%1,%2,%0;" : "+l"(d) : "l"(a), "l"(b));
}
__device__ __forceinline__ float2 f2un(u64 v) {
    float2 f; asm("mov.b64 {%0,%1},%2;" : "=f"(f.x), "=f"(f.y) : "l"(v)); return f;
}
__device__ __forceinline__ u64 f2dup(float a) {
    u64 r; asm("mov.b64 %0,{%1,%1};" : "=l"(r) : "f"(a)); return r;
}

// ---------------- device scratch ----------------
__device__ float g_q[NN * H];    // q / sqrt(H), row-major [node][m]
__device__ float g_kT[H * NN];   // k transposed  [m][node]
__device__ float g_v[NN * H];    // v row-major
__device__ float g_al[NN * H];   // alpha = 0.5*w*(u+be1), row-major
__device__ float g_bT[H * NN];   // beta  = -0.5*w*u, transposed [m][node]
__device__ float g_A[NN];
__device__ float g_B[NN];
__device__ float g_sig[H];
__device__ float g_c;

// ---------------------------------------------------------------------------
// prep: 256 blocks x 256 thr, 4 rows/block (2 rows per o-group)
// ---------------------------------------------------------------------------
__global__ __launch_bounds__(PTHREADS)
void prep_kernel(const float* __restrict__ h, const float* __restrict__ x,
                 const float* __restrict__ Wq, const float* __restrict__ bq,
                 const float* __restrict__ Wk, const float* __restrict__ bk,
                 const float* __restrict__ Wv, const float* __restrict__ bv,
                 const float* __restrict__ We1, const float* __restrict__ be1,
                 const float* __restrict__ We2, const float* __restrict__ be2,
                 const float* __restrict__ Wc, const float* __restrict__ bc)
{
    __shared__ float hs[PROWS * H];
    __shared__ float xs2[PROWS][2];
    __shared__ float ws[H];
    __shared__ float part[128];
    __shared__ float wpart[8][2][2];
    int t = threadIdx.x;
    int r0 = blockIdx.x * PROWS;

    for (int idx = t; idx < PROWS * H; idx += PTHREADS) hs[idx] = h[r0 * H + idx];
    if (t < PROWS * 2) xs2[t >> 1][t & 1] = x[r0 * 2 + t];

    // ---- fold w = We2 @ Wc (redundant per block; only block 0 publishes) ----
    {
        int m = t >> 1, half = t & 1;
        const float* row = We2 + m * H + half * 64;
        const float* wc  = Wc + half * 64;
        float acc = 0.f;
#pragma unroll 16
        for (int o = 0; o < 64; ++o) acc = fmaf(row[o], wc[o], acc);
        acc += __shfl_xor_sync(0xffffffffu, acc, 1);
        if (!half) {
            ws[m] = acc;
            if (blockIdx.x == 0) g_sig[m] = (acc >= 0.f) ? 1.0f : -1.0f;
        }
    }
    if (t < 128) part[t] = be2[t] * Wc[t];
    __syncthreads();
    for (int s = 64; s > 0; s >>= 1) {
        if (t < s) part[t] += part[t + s];
        __syncthreads();
    }
    if (t == 0 && blockIdx.x == 0) g_c = part[0] + bc[0];

    // ---- qkv GEMV: group g handles rows 2g, 2g+1 ----
    int o = t & 127;
    int g = t >> 7;   // 0..1
    const float SCALE = 0.08838834764831845f;

    float aq[2], ak[2], av[2];
    float bqv = bq[o], bkv = bk[o], bvv = bv[o];
#pragma unroll
    for (int r = 0; r < 2; ++r) { aq[r] = bqv; ak[r] = bkv; av[r] = bvv; }

#pragma unroll 4
    for (int m = 0; m < H; ++m) {
        float wq = Wq[m * H + o];
        float wk = Wk[m * H + o];
        float wv = Wv[m * H + o];
#pragma unroll
        for (int r = 0; r < 2; ++r) {
            float hm = hs[(g * 2 + r) * H + m];
            aq[r] = fmaf(hm, wq, aq[r]);
            ak[r] = fmaf(hm, wk, ak[r]);
            av[r] = fmaf(hm, wv, av[r]);
        }
    }
#pragma unroll
    for (int r = 0; r < 2; ++r) {
        int row = r0 + g * 2 + r;
        g_q[row * H + o] = aq[r] * SCALE;
        g_kT[o * NN + row] = ak[r];
        g_v[row * H + o] = av[r];
    }

    float w0 = We1[o], w1 = We1[H + o], b1 = be1[o], wo = ws[o];
    float sA[2], sB[2];
#pragma unroll
    for (int r = 0; r < 2; ++r) {
        int row = r0 + g * 2 + r;
        float u  = fmaf(xs2[g * 2 + r][0], w0, xs2[g * 2 + r][1] * w1);
        float ub = u + b1;
        float al = 0.5f * wo * ub;
        float be = -0.5f * wo * u;
        g_al[row * H + o] = al;
        g_bT[o * NN + row] = be;
        sA[r] = al; sB[r] = be;
    }
#pragma unroll
    for (int s = 16; s > 0; s >>= 1) {
#pragma unroll
        for (int r = 0; r < 2; ++r) {
            sA[r] += __shfl_xor_sync(0xffffffffu, sA[r], s);
            sB[r] += __shfl_xor_sync(0xffffffffu, sB[r], s);
        }
    }
    int wr = t >> 5, lane = t & 31;
    if (lane == 0) {
#pragma unroll
        for (int r = 0; r < 2; ++r) { wpart[wr][r][0] = sA[r]; wpart[wr][r][1] = sB[r]; }
    }
    __syncthreads();
    if (t < PROWS) {
        int i = t;                 // local row
        int gg = i >> 1, rr = i & 1;
        float A = 0.f, B = 0.f;
#pragma unroll
        for (int ww = 0; ww < 4; ++ww) {
            A += wpart[4 * gg + ww][rr][0];
            B += wpart[4 * gg + ww][rr][1];
        }
        g_A[r0 + i] = A;
        g_B[r0 + i] = B;
    }
}

// ---------------------------------------------------------------------------
// main: 128 blocks x 1024 threads (32 warps). Thread owns 1 j, all 8 i.
// ---------------------------------------------------------------------------
#define SM_QD   0        // 128*8 q [m][i]
#define SM_AD   1024     // 128*8 alpha
#define SM_SD   2048     // 128*2 dup sig
#define SM_XI   2304     // 16
#define SM_ASH  2320     // 8
#define SM_SMX  2328     // 32
#define SM_SSUM 2360     // 32
#define SM_DXS  2392     // 32*16
#define SM_P    2904     // 8*1024 scores [i][j]
#define SM_AVP  11096    // 32*8*128 AV partials
#define SMEM_FLOATS (SM_AVP + 32768)

__global__ __launch_bounds__(THREADS, 1)
void main_kernel(const float* __restrict__ h, const float* __restrict__ x,
                 float* __restrict__ out_h, float* __restrict__ out_x)
{
    extern __shared__ float sm[];
    float* Qd  = sm + SM_QD;
    float* Ad  = sm + SM_AD;
    float* Sd  = sm + SM_SD;
    float* XI  = sm + SM_XI;
    float* ASH = sm + SM_ASH;
    float* SMX = sm + SM_SMX;
    float* SSUM= sm + SM_SSUM;
    float* DXS = sm + SM_DXS;
    float* P   = sm + SM_P;
    float* AVP = sm + SM_AVP;

    int t = threadIdx.x;
    int i0 = blockIdx.x * 8;
    int w = t >> 5, l = t & 31;

    for (int idx = t; idx < 1024; idx += THREADS) {
        int i = idx & 7, m = idx >> 3;
        Qd[m * 8 + i] = g_q[(i0 + i) * H + m];
        Ad[m * 8 + i] = g_al[(i0 + i) * H + m];
    }
    if (t < H) { float s = g_sig[t]; Sd[2 * t] = s; Sd[2 * t + 1] = s; }
    if (t < 16) XI[t] = x[i0 * 2 + t];
    if (t < 8)  ASH[t] = g_c + g_A[i0 + t];
    __syncthreads();

    // ============ Fused score + gate m-loop (thread owns j = t) ============
    u64 acc[4], ga[4];
#pragma unroll
    for (int ip = 0; ip < 4; ++ip) { acc[ip] = 0ull; ga[ip] = 0ull; }
#pragma unroll 4
    for (int m = 0; m < H; ++m) {
        u64 kd = f2dup(g_kT[m * NN + t]);
        u64 bd = f2dup(g_bT[m * NN + t]);
        u64 sd = *(const u64*)(Sd + 2 * m);
        ulonglong2 qA = *(const ulonglong2*)(Qd + m * 8);
        ulonglong2 qB = *(const ulonglong2*)(Qd + m * 8 + 4);
        ulonglong2 aA = *(const ulonglong2*)(Ad + m * 8);
        ulonglong2 aB = *(const ulonglong2*)(Ad + m * 8 + 4);
        f2fma(acc[0], qA.x, kd);
        f2fma(acc[1], qA.y, kd);
        f2fma(acc[2], qB.x, kd);
        f2fma(acc[3], qB.y, kd);
        u64 z;
        z = f2add(aA.x, bd) & ABSM; f2fma(ga[0], z, sd);
        z = f2add(aA.y, bd) & ABSM; f2fma(ga[1], z, sd);
        z = f2add(aB.x, bd) & ABSM; f2fma(ga[2], z, sd);
        z = f2add(aB.y, bd) & ABSM; f2fma(ga[3], z, sd);
    }
#pragma unroll
    for (int ip = 0; ip < 4; ++ip) {
        float2 f = f2un(acc[ip]);
        P[(2 * ip) * NN + t]     = f.x;
        P[(2 * ip + 1) * NN + t] = f.y;
    }
    __syncthreads();

    // ============ Softmax: 4 warps per row (quarters) ============
    {
        int row = w >> 2, qt = w & 3;
        float* prow = P + row * NN + qt * 256;
        float mx = -1e30f;
        for (int j = l; j < 256; j += 32) mx = fmaxf(mx, prow[j]);
#pragma unroll
        for (int s = 16; s > 0; s >>= 1)
            mx = fmaxf(mx, __shfl_xor_sync(0xffffffffu, mx, s));
        if (l == 0) SMX[w] = mx;
        __syncthreads();
        float M = fmaxf(fmaxf(SMX[row * 4], SMX[row * 4 + 1]),
                        fmaxf(SMX[row * 4 + 2], SMX[row * 4 + 3]));
        float sum = 0.f;
        for (int j = l; j < 256; j += 32) {
            float e = __expf(prow[j] - M);
            prow[j] = e;
            sum += e;
        }
#pragma unroll
        for (int s = 16; s > 0; s >>= 1)
            sum += __shfl_xor_sync(0xffffffffu, sum, s);
        if (l == 0) SSUM[w] = sum;
        __syncthreads();
        float inv = 1.f / (SSUM[row * 4] + SSUM[row * 4 + 1]
                         + SSUM[row * 4 + 2] + SSUM[row * 4 + 3]);
        for (int j = l; j < 256; j += 32) prow[j] *= inv;
    }
    __syncthreads();

    // ============ Gate combine: delta_x (thread owns j = t) ============
    {
        float Bj = g_B[t];
        float2 xj = *(const float2*)(x + 2 * t);
        float dxv[8], dyv[8];
#pragma unroll
        for (int ip = 0; ip < 4; ++ip) {
            float2 g2 = f2un(ga[ip]);
            int ia = 2 * ip, ib = 2 * ip + 1;
            float G0 = ASH[ia] + Bj + g2.x;
            float G1 = ASH[ib] + Bj + g2.y;
            float pg0 = P[ia * NN + t] * G0;
            float pg1 = P[ib * NN + t] * G1;
            dxv[ia] = pg0 * (XI[2 * ia]     - xj.x);
            dyv[ia] = pg0 * (XI[2 * ia + 1] - xj.y);
            dxv[ib] = pg1 * (XI[2 * ib]     - xj.x);
            dyv[ib] = pg1 * (XI[2 * ib + 1] - xj.y);
        }
#pragma unroll
        for (int s = 16; s > 0; s >>= 1) {
#pragma unroll
            for (int i = 0; i < 8; ++i) {
                dxv[i] += __shfl_xor_sync(0xffffffffu, dxv[i], s);
                dyv[i] += __shfl_xor_sync(0xffffffffu, dyv[i], s);
            }
        }
        if (l == 0) {
#pragma unroll
            for (int i = 0; i < 8; ++i) {
                DXS[w * 16 + 2 * i]     = dxv[i];
                DXS[w * 16 + 2 * i + 1] = dyv[i];
            }
        }
    }

    // ============ AV: warp owns 32 j's, lane owns 4 cols ============
    {
        u64 av[8][2];
#pragma unroll
        for (int i = 0; i < 8; ++i) { av[i][0] = 0ull; av[i][1] = 0ull; }
        int c0 = l << 2;
        int jbase = w << 5;
#pragma unroll 2
        for (int jj = 0; jj < 32; ++jj) {
            int j = jbase + jj;
            ulonglong2 v2 = *(const ulonglong2*)(g_v + j * H + c0);
#pragma unroll
            for (int i = 0; i < 8; ++i) {
                u64 pd = f2dup(P[i * NN + j]);   // warp-uniform broadcast
                f2fma(av[i][0], pd, v2.x);
                f2fma(av[i][1], pd, v2.y);
            }
        }
        // AVP does not alias P — no barrier needed before these stores
#pragma unroll
        for (int i = 0; i < 8; ++i) {
            float2 a = f2un(av[i][0]);
            float2 b = f2un(av[i][1]);
            *(float4*)&AVP[(w * 8 + i) * 128 + c0] = make_float4(a.x, a.y, b.x, b.y);
        }
    }
    __syncthreads();

    // ============ Final reduce + epilogue ============
    {
        int i = t >> 7, c = t & 127;
        float s = 0.f;
#pragma unroll
        for (int w2 = 0; w2 < 32; ++w2)
            s += AVP[(w2 * 8 + i) * 128 + c];
        out_h[(i0 + i) * H + c] = h[(i0 + i) * H + c] + s;
    }
    if (t < 16) {
        int i = t >> 1, d = t & 1;
        float s = 0.f;
#pragma unroll
        for (int w2 = 0; w2 < 32; ++w2) s += DXS[w2 * 16 + 2 * i + d];
        out_x[(i0 + i) * 2 + d] = x[(i0 + i) * 2 + d] + s;
    }
}

// ---------------------------------------------------------------------------
extern "C" void kernel_launch(void* const* d_in, const int* in_sizes, int n_in,
                              void* d_out, int out_size)
{
    const float* h   = (const float*)d_in[0];
    const float* x   = (const float*)d_in[1];
    const float* Wq  = (const float*)d_in[3];
    const float* bq  = (const float*)d_in[4];
    const float* Wk  = (const float*)d_in[5];
    const float* bk  = (const float*)d_in[6];
    const float* Wv  = (const float*)d_in[7];
    const float* bv  = (const float*)d_in[8];
    const float* We1 = (const float*)d_in[9];
    const float* be1 = (const float*)d_in[10];
    const float* We2 = (const float*)d_in[11];
    const float* be2 = (const float*)d_in[12];
    const float* Wc  = (const float*)d_in[13];
    const float* bc  = (const float*)d_in[14];

    float* out   = (float*)d_out;
    float* out_h = out;
    float* out_x = out + NN * H;

    size_t smem_bytes = (size_t)SMEM_FLOATS * sizeof(float);
    cudaFuncSetAttribute(main_kernel,
                         cudaFuncAttributeMaxDynamicSharedMemorySize,
                         (int)smem_bytes);

    prep_kernel<<<NN / PROWS, PTHREADS>>>(h, x, Wq, bq, Wk, bk, Wv, bv,
                                          We1, be1, We2, be2, Wc, bc);
    main_kernel<<<NN / 8, THREADS, smem_bytes>>>(h, x, out_h, out_x);
}

// round 9
// speedup vs baseline: 1.3140x; 1.3140x over previous
#include <cuda_runtime.h>
#include <math.h>

#define NN 1024
#define H 128
#define THREADS 1024    // main kernel
#define PTHREADS 256    // prep kernel

typedef unsigned long long u64;
#define ABSM 0x7FFFFFFF7FFFFFFFULL

// ---------------- f32x2 packed helpers ----------------
__device__ __forceinline__ u64 f2add(u64 a, u64 b) {
    u64 r; asm("add.rn.f32x2 %0,%1,%2;" : "=l"(r) : "l"(a), "l"(b)); return r;
}
__device__ __forceinline__ void f2fma(u64& d, u64 a, u64 b) {
    asm("fma.rn.f32x2 %0,%1,%2,%0;" : "+l"(d) : "l"(a), "l"(b));
}
__device__ __forceinline__ float2 f2un(u64 v) {
    float2 f; asm("mov.b64 {%0,%1},%2;" : "=f"(f.x), "=f"(f.y) : "l"(v)); return f;
}
__device__ __forceinline__ u64 f2dup(float a) {
    u64 r; asm("mov.b64 %0,{%1,%1};" : "=l"(r) : "f"(a)); return r;
}

// ---------------- device scratch ----------------
__device__ float g_q[NN * H];    // q / sqrt(H), row-major [node][m]
__device__ float g_kT[H * NN];   // k transposed  [m][node]
__device__ float g_v[NN * H];    // v row-major
__device__ float g_al[NN * H];   // alpha = 0.5*w*(u+be1), row-major
__device__ float g_bT[H * NN];   // beta  = -0.5*w*u, transposed [m][node]
__device__ float g_A[NN];
__device__ float g_B[NN];
__device__ float g_sig[H];
__device__ float g_c;

// ---------------------------------------------------------------------------
// prep (REVERT to measured-fast round-3 version):
// 128 blocks x 256 thr, 8 rows/block, 4 rows per thread-group
// ---------------------------------------------------------------------------
__global__ __launch_bounds__(PTHREADS)
void prep_kernel(const float* __restrict__ h, const float* __restrict__ x,
                 const float* __restrict__ Wq, const float* __restrict__ bq,
                 const float* __restrict__ Wk, const float* __restrict__ bk,
                 const float* __restrict__ Wv, const float* __restrict__ bv,
                 const float* __restrict__ We1, const float* __restrict__ be1,
                 const float* __restrict__ We2, const float* __restrict__ be2,
                 const float* __restrict__ Wc, const float* __restrict__ bc)
{
    __shared__ float hs[8 * H];
    __shared__ float xs2[8][2];
    __shared__ float ws[H];
    __shared__ float part[128];
    __shared__ float wpart[8][4][2];
    int t = threadIdx.x;
    int r0 = blockIdx.x * 8;

    for (int idx = t; idx < 8 * H; idx += PTHREADS) hs[idx] = h[r0 * H + idx];
    if (t < 16) xs2[t >> 1][t & 1] = x[r0 * 2 + t];

    {
        int m = t >> 1, half = t & 1;
        const float* row = We2 + m * H + half * 64;
        const float* wc  = Wc + half * 64;
        float acc = 0.f;
#pragma unroll 16
        for (int o = 0; o < 64; ++o) acc = fmaf(row[o], wc[o], acc);
        acc += __shfl_xor_sync(0xffffffffu, acc, 1);
        if (!half) {
            ws[m] = acc;
            if (r0 == 0) g_sig[m] = (acc >= 0.f) ? 1.0f : -1.0f;
        }
    }
    if (t < 128) part[t] = be2[t] * Wc[t];
    __syncthreads();
    for (int s = 64; s > 0; s >>= 1) {
        if (t < s) part[t] += part[t + s];
        __syncthreads();
    }
    if (t == 0 && r0 == 0) g_c = part[0] + bc[0];

    int o = t & 127;
    int g = t >> 7;
    const float SCALE = 0.08838834764831845f;

    float aq[4], ak[4], av[4];
    float bqv = bq[o], bkv = bk[o], bvv = bv[o];
#pragma unroll
    for (int r = 0; r < 4; ++r) { aq[r] = bqv; ak[r] = bkv; av[r] = bvv; }

#pragma unroll 4
    for (int m = 0; m < H; ++m) {
        float wq = Wq[m * H + o];
        float wk = Wk[m * H + o];
        float wv = Wv[m * H + o];
#pragma unroll
        for (int r = 0; r < 4; ++r) {
            float hm = hs[(g * 4 + r) * H + m];
            aq[r] = fmaf(hm, wq, aq[r]);
            ak[r] = fmaf(hm, wk, ak[r]);
            av[r] = fmaf(hm, wv, av[r]);
        }
    }
#pragma unroll
    for (int r = 0; r < 4; ++r) {
        int row = r0 + g * 4 + r;
        g_q[row * H + o] = aq[r] * SCALE;
        g_kT[o * NN + row] = ak[r];
        g_v[row * H + o] = av[r];
    }

    float w0 = We1[o], w1 = We1[H + o], b1 = be1[o], wo = ws[o];
    float sA[4], sB[4];
#pragma unroll
    for (int r = 0; r < 4; ++r) {
        int row = r0 + g * 4 + r;
        float u  = fmaf(xs2[g * 4 + r][0], w0, xs2[g * 4 + r][1] * w1);
        float ub = u + b1;
        float al = 0.5f * wo * ub;
        float be = -0.5f * wo * u;
        g_al[row * H + o] = al;
        g_bT[o * NN + row] = be;
        sA[r] = al; sB[r] = be;
    }
#pragma unroll
    for (int s = 16; s > 0; s >>= 1) {
#pragma unroll
        for (int r = 0; r < 4; ++r) {
            sA[r] += __shfl_xor_sync(0xffffffffu, sA[r], s);
            sB[r] += __shfl_xor_sync(0xffffffffu, sB[r], s);
        }
    }
    int wr = t >> 5, lane = t & 31;
    if (lane == 0) {
#pragma unroll
        for (int r = 0; r < 4; ++r) { wpart[wr][r][0] = sA[r]; wpart[wr][r][1] = sB[r]; }
    }
    __syncthreads();
    if (t < 8) {
        int gg = t >> 2, rr = t & 3;
        float A = 0.f, B = 0.f;
#pragma unroll
        for (int ww = 0; ww < 4; ++ww) {
            A += wpart[4 * gg + ww][rr][0];
            B += wpart[4 * gg + ww][rr][1];
        }
        int row = r0 + gg * 4 + rr;
        g_A[row] = A;
        g_B[row] = B;
    }
}

// ---------------------------------------------------------------------------
// main: 128 blocks x 1024 threads (32 warps). Thread owns 1 j, all 8 i.
// ---------------------------------------------------------------------------
#define SM_QD   0        // 128*8 q [m][i]
#define SM_AD   1024     // 128*8 alpha
#define SM_SD   2048     // 128*2 dup sig
#define SM_XI   2304     // 16
#define SM_ASH  2320     // 8
#define SM_SMX  2328     // 32
#define SM_SSUM 2360     // 32
#define SM_DXS  2392     // 32*16
#define SM_P    2904     // 8*1024 scores [i][j]
#define SM_AVP  11096    // 32*8*128 AV partials
#define SM_P2   (SM_AVP + 32768)   // 1024*8 transposed probs [j][i]
#define SMEM_FLOATS (SM_P2 + 8192)

__global__ __launch_bounds__(THREADS, 1)
void main_kernel(const float* __restrict__ h, const float* __restrict__ x,
                 float* __restrict__ out_h, float* __restrict__ out_x)
{
    extern __shared__ float sm[];
    float* Qd  = sm + SM_QD;
    float* Ad  = sm + SM_AD;
    float* Sd  = sm + SM_SD;
    float* XI  = sm + SM_XI;
    float* ASH = sm + SM_ASH;
    float* SMX = sm + SM_SMX;
    float* SSUM= sm + SM_SSUM;
    float* DXS = sm + SM_DXS;
    float* P   = sm + SM_P;
    float* AVP = sm + SM_AVP;
    float* P2  = sm + SM_P2;

    int t = threadIdx.x;
    int i0 = blockIdx.x * 8;
    int w = t >> 5, l = t & 31;

    for (int idx = t; idx < 1024; idx += THREADS) {
        int i = idx & 7, m = idx >> 3;
        Qd[m * 8 + i] = g_q[(i0 + i) * H + m];
        Ad[m * 8 + i] = g_al[(i0 + i) * H + m];
    }
    if (t < H) { float s = g_sig[t]; Sd[2 * t] = s; Sd[2 * t + 1] = s; }
    if (t < 16) XI[t] = x[i0 * 2 + t];
    if (t < 8)  ASH[t] = g_c + g_A[i0 + t];
    __syncthreads();

    // ============ Fused score + gate m-loop (thread owns j = t) ============
    u64 acc[4], ga[4];
#pragma unroll
    for (int ip = 0; ip < 4; ++ip) { acc[ip] = 0ull; ga[ip] = 0ull; }
#pragma unroll 4
    for (int m = 0; m < H; ++m) {
        u64 kd = f2dup(g_kT[m * NN + t]);
        u64 bd = f2dup(g_bT[m * NN + t]);
        u64 sd = *(const u64*)(Sd + 2 * m);
        ulonglong2 qA = *(const ulonglong2*)(Qd + m * 8);
        ulonglong2 qB = *(const ulonglong2*)(Qd + m * 8 + 4);
        ulonglong2 aA = *(const ulonglong2*)(Ad + m * 8);
        ulonglong2 aB = *(const ulonglong2*)(Ad + m * 8 + 4);
        f2fma(acc[0], qA.x, kd);
        f2fma(acc[1], qA.y, kd);
        f2fma(acc[2], qB.x, kd);
        f2fma(acc[3], qB.y, kd);
        u64 z;
        z = f2add(aA.x, bd) & ABSM; f2fma(ga[0], z, sd);
        z = f2add(aA.y, bd) & ABSM; f2fma(ga[1], z, sd);
        z = f2add(aB.x, bd) & ABSM; f2fma(ga[2], z, sd);
        z = f2add(aB.y, bd) & ABSM; f2fma(ga[3], z, sd);
    }
#pragma unroll
    for (int ip = 0; ip < 4; ++ip) {
        float2 f = f2un(acc[ip]);
        P[(2 * ip) * NN + t]     = f.x;
        P[(2 * ip + 1) * NN + t] = f.y;
    }
    __syncthreads();

    // ============ Softmax: 4 warps per row (quarters) ============
    {
        int row = w >> 2, qt = w & 3;
        float* prow = P + row * NN + qt * 256;
        float mx = -1e30f;
        for (int j = l; j < 256; j += 32) mx = fmaxf(mx, prow[j]);
#pragma unroll
        for (int s = 16; s > 0; s >>= 1)
            mx = fmaxf(mx, __shfl_xor_sync(0xffffffffu, mx, s));
        if (l == 0) SMX[w] = mx;
        __syncthreads();
        float M = fmaxf(fmaxf(SMX[row * 4], SMX[row * 4 + 1]),
                        fmaxf(SMX[row * 4 + 2], SMX[row * 4 + 3]));
        float sum = 0.f;
        for (int j = l; j < 256; j += 32) {
            float e = __expf(prow[j] - M);
            prow[j] = e;
            sum += e;
        }
#pragma unroll
        for (int s = 16; s > 0; s >>= 1)
            sum += __shfl_xor_sync(0xffffffffu, sum, s);
        if (l == 0) SSUM[w] = sum;
        __syncthreads();
        float inv = 1.f / (SSUM[row * 4] + SSUM[row * 4 + 1]
                         + SSUM[row * 4 + 2] + SSUM[row * 4 + 3]);
        for (int j = l; j < 256; j += 32) prow[j] *= inv;
    }
    __syncthreads();

    // ============ Gate combine: delta_x (thread owns j = t) ============
    {
        float pv[8];
#pragma unroll
        for (int i = 0; i < 8; ++i) pv[i] = P[i * NN + t];
        // transposed copy for AV phase (same-warp consumption)
        *(float4*)&P2[t * 8]     = make_float4(pv[0], pv[1], pv[2], pv[3]);
        *(float4*)&P2[t * 8 + 4] = make_float4(pv[4], pv[5], pv[6], pv[7]);
        __syncwarp();

        float Bj = g_B[t];
        float2 xj = *(const float2*)(x + 2 * t);
        float dxv[8], dyv[8];
#pragma unroll
        for (int ip = 0; ip < 4; ++ip) {
            float2 g2 = f2un(ga[ip]);
            int ia = 2 * ip, ib = 2 * ip + 1;
            float G0 = ASH[ia] + Bj + g2.x;
            float G1 = ASH[ib] + Bj + g2.y;
            float pg0 = pv[ia] * G0;
            float pg1 = pv[ib] * G1;
            dxv[ia] = pg0 * (XI[2 * ia]     - xj.x);
            dyv[ia] = pg0 * (XI[2 * ia + 1] - xj.y);
            dxv[ib] = pg1 * (XI[2 * ib]     - xj.x);
            dyv[ib] = pg1 * (XI[2 * ib + 1] - xj.y);
        }
#pragma unroll
        for (int s = 16; s > 0; s >>= 1) {
#pragma unroll
            for (int i = 0; i < 8; ++i) {
                dxv[i] += __shfl_xor_sync(0xffffffffu, dxv[i], s);
                dyv[i] += __shfl_xor_sync(0xffffffffu, dyv[i], s);
            }
        }
        if (l == 0) {
#pragma unroll
            for (int i = 0; i < 8; ++i) {
                DXS[w * 16 + 2 * i]     = dxv[i];
                DXS[w * 16 + 2 * i + 1] = dyv[i];
            }
        }
    }

    // ============ AV: warp owns 32 j's, lane owns 4 cols ============
    {
        u64 av[8][2];
#pragma unroll
        for (int i = 0; i < 8; ++i) { av[i][0] = 0ull; av[i][1] = 0ull; }
        int c0 = l << 2;
        int jbase = w << 5;
#pragma unroll 2
        for (int jj = 0; jj < 32; ++jj) {
            int j = jbase + jj;
            ulonglong2 v2 = *(const ulonglong2*)(g_v + j * H + c0);
            float4 pa = *(const float4*)&P2[j * 8];      // warp-uniform broadcast
            float4 pb = *(const float4*)&P2[j * 8 + 4];
            f2fma(av[0][0], f2dup(pa.x), v2.x); f2fma(av[0][1], f2dup(pa.x), v2.y);
            f2fma(av[1][0], f2dup(pa.y), v2.x); f2fma(av[1][1], f2dup(pa.y), v2.y);
            f2fma(av[2][0], f2dup(pa.z), v2.x); f2fma(av[2][1], f2dup(pa.z), v2.y);
            f2fma(av[3][0], f2dup(pa.w), v2.x); f2fma(av[3][1], f2dup(pa.w), v2.y);
            f2fma(av[4][0], f2dup(pb.x), v2.x); f2fma(av[4][1], f2dup(pb.x), v2.y);
            f2fma(av[5][0], f2dup(pb.y), v2.x); f2fma(av[5][1], f2dup(pb.y), v2.y);
            f2fma(av[6][0], f2dup(pb.z), v2.x); f2fma(av[6][1], f2dup(pb.z), v2.y);
            f2fma(av[7][0], f2dup(pb.w), v2.x); f2fma(av[7][1], f2dup(pb.w), v2.y);
        }
#pragma unroll
        for (int i = 0; i < 8; ++i) {
            float2 a = f2un(av[i][0]);
            float2 b = f2un(av[i][1]);
            *(float4*)&AVP[(w * 8 + i) * 128 + c0] = make_float4(a.x, a.y, b.x, b.y);
        }
    }
    __syncthreads();

    // ============ Final reduce + epilogue ============
    {
        int i = t >> 7, c = t & 127;
        float s = 0.f;
#pragma unroll
        for (int w2 = 0; w2 < 32; ++w2)
            s += AVP[(w2 * 8 + i) * 128 + c];
        out_h[(i0 + i) * H + c] = h[(i0 + i) * H + c] + s;
    }
    if (t < 16) {
        int i = t >> 1, d = t & 1;
        float s = 0.f;
#pragma unroll
        for (int w2 = 0; w2 < 32; ++w2) s += DXS[w2 * 16 + 2 * i + d];
        out_x[(i0 + i) * 2 + d] = x[(i0 + i) * 2 + d] + s;
    }
}

// ---------------------------------------------------------------------------
extern "C" void kernel_launch(void* const* d_in, const int* in_sizes, int n_in,
                              void* d_out, int out_size)
{
    const float* h   = (const float*)d_in[0];
    const float* x   = (const float*)d_in[1];
    const float* Wq  = (const float*)d_in[3];
    const float* bq  = (const float*)d_in[4];
    const float* Wk  = (const float*)d_in[5];
    const float* bk  = (const float*)d_in[6];
    const float* Wv  = (const float*)d_in[7];
    const float* bv  = (const float*)d_in[8];
    const float* We1 = (const float*)d_in[9];
    const float* be1 = (const float*)d_in[10];
    const float* We2 = (const float*)d_in[11];
    const float* be2 = (const float*)d_in[12];
    const float* Wc  = (const float*)d_in[13];
    const float* bc  = (const float*)d_in[14];

    float* out   = (float*)d_out;
    float* out_h = out;
    float* out_x = out + NN * H;

    size_t smem_bytes = (size_t)SMEM_FLOATS * sizeof(float);
    cudaFuncSetAttribute(main_kernel,
                         cudaFuncAttributeMaxDynamicSharedMemorySize,
                         (int)smem_bytes);

    prep_kernel<<<NN / 8, PTHREADS>>>(h, x, Wq, bq, Wk, bk, Wv, bv,
                                      We1, be1, We2, be2, Wc, bc);
    main_kernel<<<NN / 8, THREADS, smem_bytes>>>(h, x, out_h, out_x);
}

// round 12
// speedup vs baseline: 1.3513x; 1.0284x over previous
#include <cuda_runtime.h>
#include <math.h>

#define NN 1024
#define H 128
#define THREADS 1024
#define NBLOCKS (NN / 8)

typedef unsigned long long u64;
#define ABSM 0x7FFFFFFF7FFFFFFFULL

// ---------------- f32x2 packed helpers ----------------
__device__ __forceinline__ u64 f2add(u64 a, u64 b) {
    u64 r; asm("add.rn.f32x2 %0,%1,%2;" : "=l"(r) : "l"(a), "l"(b)); return r;
}
__device__ __forceinline__ void f2fma(u64& d, u64 a, u64 b) {
    asm("fma.rn.f32x2 %0,%1,%2,%0;" : "+l"(d) : "l"(a), "l"(b));
}
__device__ __forceinline__ float2 f2un(u64 v) {
    float2 f; asm("mov.b64 {%0,%1},%2;" : "=f"(f.x), "=f"(f.y) : "l"(v)); return f;
}
__device__ __forceinline__ u64 f2dup(float a) {
    u64 r; asm("mov.b64 %0,{%1,%1};" : "=l"(r) : "f"(a)); return r;
}

// ---------------- device scratch ----------------
__device__ float g_kbT[H * NN * 2];  // interleaved [m][2j]={k, beta}
__device__ float g_v[NN * H];        // v row-major
__device__ float g_B[NN];            // sum_m beta

// ---------------- grid barrier state ----------------
__device__ unsigned bar_cnt;
__device__ volatile unsigned bar_gen;

// ---------------- smem layout (floats) ----------------
#define SM_QD   0        // 128*8 q [m][i]
#define SM_AD   1024     // 128*8 alpha
#define SM_SD   2048     // 128*2 dup sig
#define SM_XI   2304     // 16
#define SM_ASH  2320     // 8
#define SM_SMX  2328     // 32
#define SM_SSUM 2360     // 32
#define SM_DXS  2392     // 32*16
#define SM_P    2904     // 8*1024 scores [i][j]  (phase-1 scratch overlays here)
#define SM_AVP  11096    // 32*8*128 AV partials
#define SM_P2   43864    // 1024*8 transposed probs [j][i]
#define SMEM_FLOATS (SM_P2 + 8192)

// phase-1 scratch overlay inside P region
#define PH_HS   SM_P            // 1024
#define PH_PART (SM_P + 1024)   // 128
#define PH_WP   (SM_P + 1152)   // 64  (wpart[8][4][2])
#define PH_WS   (SM_P + 1216)   // 128
#define PH_XS   (SM_P + 1344)   // 16
#define PH_CV   (SM_P + 1360)   // 1

__global__ __launch_bounds__(THREADS, 1)
void fused_kernel(const float* __restrict__ h, const float* __restrict__ x,
                  const float* __restrict__ Wq, const float* __restrict__ bq,
                  const float* __restrict__ Wk, const float* __restrict__ bk,
                  const float* __restrict__ Wv, const float* __restrict__ bv,
                  const float* __restrict__ We1, const float* __restrict__ be1,
                  const float* __restrict__ We2, const float* __restrict__ be2,
                  const float* __restrict__ Wc, const float* __restrict__ bc,
                  float* __restrict__ out_h, float* __restrict__ out_x)
{
    extern __shared__ float sm[];
    float* Qd  = sm + SM_QD;
    float* Ad  = sm + SM_AD;
    float* Sd  = sm + SM_SD;
    float* XI  = sm + SM_XI;
    float* ASH = sm + SM_ASH;
    float* SMX = sm + SM_SMX;
    float* SSUM= sm + SM_SSUM;
    float* DXS = sm + SM_DXS;
    float* P   = sm + SM_P;
    float* AVP = sm + SM_AVP;
    float* P2  = sm + SM_P2;
    float* hs   = sm + PH_HS;
    float* part = sm + PH_PART;
    float* wpart= sm + PH_WP;
    float* ws   = sm + PH_WS;
    float* xs2  = sm + PH_XS;
    float* cv   = sm + PH_CV;

    int t = threadIdx.x;
    int i0 = blockIdx.x * 8;
    int r0 = i0;
    int w = t >> 5, l = t & 31;

    // ===================== PHASE 1: prep (block's own 8 rows) ==============
    hs[t] = h[r0 * H + t];                 // 8*128 = 1024 loads
    if (t < 16) { xs2[t] = x[r0 * 2 + t]; XI[t] = xs2[t]; }

    // w-fold: ws[m] = We2[m,:]@Wc (threads 0..255, 2 per m)
    if (t < 256) {
        int m = t >> 1, half = t & 1;
        const float* row = We2 + m * H + half * 64;
        const float* wc  = Wc + half * 64;
        float acc = 0.f;
#pragma unroll 16
        for (int o = 0; o < 64; ++o) acc = fmaf(row[o], wc[o], acc);
        acc += __shfl_xor_sync(0xffffffffu, acc, 1);
        if (!half) ws[m] = acc;
    }
    if (t < 128) part[t] = be2[t] * Wc[t];
    __syncthreads();
    for (int s = 64; s > 0; s >>= 1) {
        if (t < s) part[t] += part[t + s];
        __syncthreads();
    }
    if (t == 0) cv[0] = part[0] + bc[0];
    if (t < 128) { float s = (ws[t] >= 0.f) ? 1.0f : -1.0f; Sd[2 * t] = s; Sd[2 * t + 1] = s; }

    if (t < 256) {
        int o = t & 127;
        int g = t >> 7;
        const float SCALE = 0.08838834764831845f;  // 1/sqrt(128)

        float aq[4], ak[4], av[4];
        float bqv = bq[o], bkv = bk[o], bvv = bv[o];
#pragma unroll
        for (int r = 0; r < 4; ++r) { aq[r] = bqv; ak[r] = bkv; av[r] = bvv; }

#pragma unroll 4
        for (int m = 0; m < H; ++m) {
            float wq = Wq[m * H + o];
            float wk = Wk[m * H + o];
            float wv = Wv[m * H + o];
#pragma unroll
            for (int r = 0; r < 4; ++r) {
                float hm = hs[(g * 4 + r) * H + m];
                aq[r] = fmaf(hm, wq, aq[r]);
                ak[r] = fmaf(hm, wk, ak[r]);
                av[r] = fmaf(hm, wv, av[r]);
            }
        }

        float w0 = We1[o], w1 = We1[H + o], b1 = be1[o], wo = ws[o];
        float al[4], be[4], sA[4], sB[4];
#pragma unroll
        for (int r = 0; r < 4; ++r) {
            float u  = fmaf(xs2[(g * 4 + r) * 2], w0, xs2[(g * 4 + r) * 2 + 1] * w1);
            al[r] = 0.5f * wo * (u + b1);
            be[r] = -0.5f * wo * u;
            sA[r] = al[r]; sB[r] = be[r];
        }
        // q/alpha straight into smem (only this block uses them)
        *(float4*)&Qd[o * 8 + g * 4] = make_float4(aq[0] * SCALE, aq[1] * SCALE,
                                                   aq[2] * SCALE, aq[3] * SCALE);
        *(float4*)&Ad[o * 8 + g * 4] = make_float4(al[0], al[1], al[2], al[3]);
        // k/beta interleaved + v to global
#pragma unroll
        for (int r = 0; r < 4; ++r) {
            int row = r0 + g * 4 + r;
            *(float2*)&g_kbT[o * (2 * NN) + 2 * row] = make_float2(ak[r], be[r]);
            g_v[row * H + o] = av[r];
        }
#pragma unroll
        for (int s = 16; s > 0; s >>= 1) {
#pragma unroll
            for (int r = 0; r < 4; ++r) {
                sA[r] += __shfl_xor_sync(0xffffffffu, sA[r], s);
                sB[r] += __shfl_xor_sync(0xffffffffu, sB[r], s);
            }
        }
        if (l == 0) {
#pragma unroll
            for (int r = 0; r < 4; ++r) {
                wpart[(w * 4 + r) * 2]     = sA[r];
                wpart[(w * 4 + r) * 2 + 1] = sB[r];
            }
        }
    }
    __syncthreads();
    if (t < 8) {
        int gg = t >> 2, rr = t & 3;
        float A = 0.f, B = 0.f;
#pragma unroll
        for (int ww = 0; ww < 4; ++ww) {
            A += wpart[((4 * gg + ww) * 4 + rr) * 2];
            B += wpart[((4 * gg + ww) * 4 + rr) * 2 + 1];
        }
        ASH[t] = cv[0] + A;
        g_B[r0 + t] = B;
    }

    // ===================== GRID BARRIER ====================================
    __syncthreads();
    if (t == 0) {
        __threadfence();
        unsigned g = bar_gen;
        if (atomicAdd(&bar_cnt, 1) == (unsigned)(gridDim.x - 1)) {
            bar_cnt = 0;
            __threadfence();
            bar_gen = g + 1;
        } else {
            while (bar_gen == g) { __nanosleep(64); }
            __threadfence();
        }
    }
    __syncthreads();

    // ===================== PHASE 2: fused attention ========================
    // Fused score + gate m-loop (thread owns j = t)
    u64 acc[4], ga[4];
#pragma unroll
    for (int ip = 0; ip < 4; ++ip) { acc[ip] = 0ull; ga[ip] = 0ull; }
#pragma unroll 4
    for (int m = 0; m < H; ++m) {
        float2 kb = *(const float2*)(g_kbT + m * (2 * NN) + 2 * t);
        u64 kd = f2dup(kb.x);
        u64 bd = f2dup(kb.y);
        u64 sd = *(const u64*)(Sd + 2 * m);
        ulonglong2 qA = *(const ulonglong2*)(Qd + m * 8);
        ulonglong2 qB = *(const ulonglong2*)(Qd + m * 8 + 4);
        ulonglong2 aA = *(const ulonglong2*)(Ad + m * 8);
        ulonglong2 aB = *(const ulonglong2*)(Ad + m * 8 + 4);
        f2fma(acc[0], qA.x, kd);
        f2fma(acc[1], qA.y, kd);
        f2fma(acc[2], qB.x, kd);
        f2fma(acc[3], qB.y, kd);
        u64 z;
        z = f2add(aA.x, bd) & ABSM; f2fma(ga[0], z, sd);
        z = f2add(aA.y, bd) & ABSM; f2fma(ga[1], z, sd);
        z = f2add(aB.x, bd) & ABSM; f2fma(ga[2], z, sd);
        z = f2add(aB.y, bd) & ABSM; f2fma(ga[3], z, sd);
    }
#pragma unroll
    for (int ip = 0; ip < 4; ++ip) {
        float2 f = f2un(acc[ip]);
        P[(2 * ip) * NN + t]     = f.x;
        P[(2 * ip + 1) * NN + t] = f.y;
    }
    __syncthreads();

    // Softmax: 4 warps per row (quarters)
    {
        int row = w >> 2, qt = w & 3;
        float* prow = P + row * NN + qt * 256;
        float mx = -1e30f;
        for (int j = l; j < 256; j += 32) mx = fmaxf(mx, prow[j]);
#pragma unroll
        for (int s = 16; s > 0; s >>= 1)
            mx = fmaxf(mx, __shfl_xor_sync(0xffffffffu, mx, s));
        if (l == 0) SMX[w] = mx;
        __syncthreads();
        float M = fmaxf(fmaxf(SMX[row * 4], SMX[row * 4 + 1]),
                        fmaxf(SMX[row * 4 + 2], SMX[row * 4 + 3]));
        float sum = 0.f;
        for (int j = l; j < 256; j += 32) {
            float e = __expf(prow[j] - M);
            prow[j] = e;
            sum += e;
        }
#pragma unroll
        for (int s = 16; s > 0; s >>= 1)
            sum += __shfl_xor_sync(0xffffffffu, sum, s);
        if (l == 0) SSUM[w] = sum;
        __syncthreads();
        float inv = 1.f / (SSUM[row * 4] + SSUM[row * 4 + 1]
                         + SSUM[row * 4 + 2] + SSUM[row * 4 + 3]);
        for (int j = l; j < 256; j += 32) prow[j] *= inv;
    }
    __syncthreads();

    // Gate combine: delta_x (thread owns j = t)
    {
        float pv[8];
#pragma unroll
        for (int i = 0; i < 8; ++i) pv[i] = P[i * NN + t];
        *(float4*)&P2[t * 8]     = make_float4(pv[0], pv[1], pv[2], pv[3]);
        *(float4*)&P2[t * 8 + 4] = make_float4(pv[4], pv[5], pv[6], pv[7]);
        __syncwarp();

        float Bj = g_B[t];
        float2 xj = *(const float2*)(x + 2 * t);
        float dxv[8], dyv[8];
#pragma unroll
        for (int ip = 0; ip < 4; ++ip) {
            float2 g2 = f2un(ga[ip]);
            int ia = 2 * ip, ib = 2 * ip + 1;
            float G0 = ASH[ia] + Bj + g2.x;
            float G1 = ASH[ib] + Bj + g2.y;
            float pg0 = pv[ia] * G0;
            float pg1 = pv[ib] * G1;
            dxv[ia] = pg0 * (XI[2 * ia]     - xj.x);
            dyv[ia] = pg0 * (XI[2 * ia + 1] - xj.y);
            dxv[ib] = pg1 * (XI[2 * ib]     - xj.x);
            dyv[ib] = pg1 * (XI[2 * ib + 1] - xj.y);
        }
#pragma unroll
        for (int s = 16; s > 0; s >>= 1) {
#pragma unroll
            for (int i = 0; i < 8; ++i) {
                dxv[i] += __shfl_xor_sync(0xffffffffu, dxv[i], s);
                dyv[i] += __shfl_xor_sync(0xffffffffu, dyv[i], s);
            }
        }
        if (l == 0) {
#pragma unroll
            for (int i = 0; i < 8; ++i) {
                DXS[w * 16 + 2 * i]     = dxv[i];
                DXS[w * 16 + 2 * i + 1] = dyv[i];
            }
        }
    }

    // AV: warp owns 32 j's, lane owns 4 cols
    {
        u64 av[8][2];
#pragma unroll
        for (int i = 0; i < 8; ++i) { av[i][0] = 0ull; av[i][1] = 0ull; }
        int c0 = l << 2;
        int jbase = w << 5;
#pragma unroll 2
        for (int jj = 0; jj < 32; ++jj) {
            int j = jbase + jj;
            ulonglong2 v2 = *(const ulonglong2*)(g_v + j * H + c0);
            float4 pa = *(const float4*)&P2[j * 8];
            float4 pb = *(const float4*)&P2[j * 8 + 4];
            f2fma(av[0][0], f2dup(pa.x), v2.x); f2fma(av[0][1], f2dup(pa.x), v2.y);
            f2fma(av[1][0], f2dup(pa.y), v2.x); f2fma(av[1][1], f2dup(pa.y), v2.y);
            f2fma(av[2][0], f2dup(pa.z), v2.x); f2fma(av[2][1], f2dup(pa.z), v2.y);
            f2fma(av[3][0], f2dup(pa.w), v2.x); f2fma(av[3][1], f2dup(pa.w), v2.y);
            f2fma(av[4][0], f2dup(pb.x), v2.x); f2fma(av[4][1], f2dup(pb.x), v2.y);
            f2fma(av[5][0], f2dup(pb.y), v2.x); f2fma(av[5][1], f2dup(pb.y), v2.y);
            f2fma(av[6][0], f2dup(pb.z), v2.x); f2fma(av[6][1], f2dup(pb.z), v2.y);
            f2fma(av[7][0], f2dup(pb.w), v2.x); f2fma(av[7][1], f2dup(pb.w), v2.y);
        }
#pragma unroll
        for (int i = 0; i < 8; ++i) {
            float2 a = f2un(av[i][0]);
            float2 b = f2un(av[i][1]);
            *(float4*)&AVP[(w * 8 + i) * 128 + c0] = make_float4(a.x, a.y, b.x, b.y);
        }
    }
    __syncthreads();

    // Final reduce + epilogue
    {
        int i = t >> 7, c = t & 127;
        float s = 0.f;
#pragma unroll
        for (int w2 = 0; w2 < 32; ++w2)
            s += AVP[(w2 * 8 + i) * 128 + c];
        out_h[(i0 + i) * H + c] = h[(i0 + i) * H + c] + s;
    }
    if (t < 16) {
        int i = t >> 1, d = t & 1;
        float s = 0.f;
#pragma unroll
        for (int w2 = 0; w2 < 32; ++w2) s += DXS[w2 * 16 + 2 * i + d];
        out_x[(i0 + i) * 2 + d] = x[(i0 + i) * 2 + d] + s;
    }
}

// ---------------------------------------------------------------------------
extern "C" void kernel_launch(void* const* d_in, const int* in_sizes, int n_in,
                              void* d_out, int out_size)
{
    const float* h   = (const float*)d_in[0];
    const float* x   = (const float*)d_in[1];
    const float* Wq  = (const float*)d_in[3];
    const float* bq  = (const float*)d_in[4];
    const float* Wk  = (const float*)d_in[5];
    const float* bk  = (const float*)d_in[6];
    const float* Wv  = (const float*)d_in[7];
    const float* bv  = (const float*)d_in[8];
    const float* We1 = (const float*)d_in[9];
    const float* be1 = (const float*)d_in[10];
    const float* We2 = (const float*)d_in[11];
    const float* be2 = (const float*)d_in[12];
    const float* Wc  = (const float*)d_in[13];
    const float* bc  = (const float*)d_in[14];

    float* out   = (float*)d_out;
    float* out_h = out;
    float* out_x = out + NN * H;

    size_t smem_bytes = (size_t)SMEM_FLOATS * sizeof(float);
    cudaFuncSetAttribute(fused_kernel,
                         cudaFuncAttributeMaxDynamicSharedMemorySize,
                         (int)smem_bytes);

    fused_kernel<<<NBLOCKS, THREADS, smem_bytes>>>(
        h, x, Wq, bq, Wk, bk, Wv, bv, We1, be1, We2, be2, Wc, bc,
        out_h, out_x);
}

// round 13
// speedup vs baseline: 1.5008x; 1.1107x over previous
#include <cuda_runtime.h>
#include <math.h>

#define NN 1024
#define H 128
#define THREADS 1024
#define NBLOCKS (NN / 8)

typedef unsigned long long u64;
#define ABSM 0x7FFFFFFF7FFFFFFFULL

// ---------------- f32x2 packed helpers ----------------
__device__ __forceinline__ u64 f2add(u64 a, u64 b) {
    u64 r; asm("add.rn.f32x2 %0,%1,%2;" : "=l"(r) : "l"(a), "l"(b)); return r;
}
__device__ __forceinline__ void f2fma(u64& d, u64 a, u64 b) {
    asm("fma.rn.f32x2 %0,%1,%2,%0;" : "+l"(d) : "l"(a), "l"(b));
}
__device__ __forceinline__ float2 f2un(u64 v) {
    float2 f; asm("mov.b64 {%0,%1},%2;" : "=f"(f.x), "=f"(f.y) : "l"(v)); return f;
}
__device__ __forceinline__ u64 f2dup(float a) {
    u64 r; asm("mov.b64 %0,{%1,%1};" : "=l"(r) : "f"(a)); return r;
}

// ---------------- device scratch ----------------
__device__ float g_kbT[(H + 8) * NN * 2];  // interleaved [m][2j]={k,beta}, +8 pad rows for prefetch
__device__ float g_v[NN * H];              // v row-major
__device__ float g_B[NN];                  // sum_m beta

// ---------------- grid barrier state ----------------
__device__ unsigned bar_cnt;
__device__ volatile unsigned bar_gen;

// ---------------- smem layout (floats) ----------------
#define SM_QD   0        // 128*8 q [m][i]
#define SM_AD   1024     // 128*8 alpha
#define SM_SD   2048     // 128*2 dup sig
#define SM_XI   2304     // 16
#define SM_ASH  2320     // 8
#define SM_SMX  2328     // 32
#define SM_SSUM 2360     // 32
#define SM_DXS  2392     // 32*16
#define SM_WP2  2648     // 64 (per-warp A/B partials)
#define SM_P    2904     // 8*1024 scores [i][j]  (phase-1 hs overlays here)
#define SM_AVP  11096    // 32*8*128 AV partials (phase-1 GEMV partials overlay)
#define SM_P2   43864    // 1024*8 transposed probs [j][i]
#define SMEM_FLOATS (SM_P2 + 8192)

// phase-1 overlays
#define PH_HS   SM_P             // 1024 floats (h rows)
#define PH_WS   (SM_P + 1024)    // 128
#define PH_XS   (SM_P + 1152)    // 16
#define PH_CP   (SM_P + 1168)    // 4
#define PH_CV   (SM_P + 1172)    // 1
// GEMV partials in AVP region, stride-9 padded: [seg*128+o]*9 + row
#define PH_PQ   SM_AVP                 // 4608
#define PH_PK   (SM_AVP + 4608)        // 4608
#define PH_PV   (SM_AVP + 9216)        // 4608

__global__ __launch_bounds__(THREADS, 1)
void fused_kernel(const float* __restrict__ h, const float* __restrict__ x,
                  const float* __restrict__ Wq, const float* __restrict__ bq,
                  const float* __restrict__ Wk, const float* __restrict__ bk,
                  const float* __restrict__ Wv, const float* __restrict__ bv,
                  const float* __restrict__ We1, const float* __restrict__ be1,
                  const float* __restrict__ We2, const float* __restrict__ be2,
                  const float* __restrict__ Wc, const float* __restrict__ bc,
                  float* __restrict__ out_h, float* __restrict__ out_x)
{
    extern __shared__ float sm[];
    float* Qd  = sm + SM_QD;
    float* Ad  = sm + SM_AD;
    float* Sd  = sm + SM_SD;
    float* XI  = sm + SM_XI;
    float* ASH = sm + SM_ASH;
    float* SMX = sm + SM_SMX;
    float* SSUM= sm + SM_SSUM;
    float* DXS = sm + SM_DXS;
    float* WP2 = sm + SM_WP2;
    float* P   = sm + SM_P;
    float* AVP = sm + SM_AVP;
    float* P2  = sm + SM_P2;
    float* hs  = sm + PH_HS;
    float* ws  = sm + PH_WS;
    float* xs2 = sm + PH_XS;
    float* cp  = sm + PH_CP;
    float* cv  = sm + PH_CV;

    int t = threadIdx.x;
    int i0 = blockIdx.x * 8;
    int r0 = i0;
    int w = t >> 5, l = t & 31;

    // ===================== PHASE 1 =========================================
    hs[t] = h[r0 * H + t];
    if (t < 16) { float xv = x[r0 * 2 + t]; xs2[t] = xv; XI[t] = xv; }
    __syncthreads();

    // ---- GEMV partials: seg = t>>8 owns m in [seg*32, seg*32+32) ----
    {
        int seg = t >> 8;
        int sub = t & 255;
        int o = sub & 127;
        int g = sub >> 7;           // row group: rows g*4..g*4+3
        int m0 = seg * 32;

        float aq[4] = {0.f, 0.f, 0.f, 0.f};
        float ak[4] = {0.f, 0.f, 0.f, 0.f};
        float av[4] = {0.f, 0.f, 0.f, 0.f};
#pragma unroll 4
        for (int mm = 0; mm < 32; ++mm) {
            int m = m0 + mm;
            float wq = Wq[m * H + o];
            float wk = Wk[m * H + o];
            float wv = Wv[m * H + o];
#pragma unroll
            for (int r = 0; r < 4; ++r) {
                float hm = hs[(g * 4 + r) * H + m];
                aq[r] = fmaf(hm, wq, aq[r]);
                ak[r] = fmaf(hm, wk, ak[r]);
                av[r] = fmaf(hm, wv, av[r]);
            }
        }
        int pb = (seg * 128 + o) * 9 + g * 4;
#pragma unroll
        for (int r = 0; r < 4; ++r) {
            sm[PH_PQ + pb + r] = aq[r];
            sm[PH_PK + pb + r] = ak[r];
            sm[PH_PV + pb + r] = av[r];
        }
    }

    // ---- w-fold: ws[m] = We2[m,:]@Wc (threads 0..255) ----
    if (t < 256) {
        int m = t >> 1, half = t & 1;
        const float* row = We2 + m * H + half * 64;
        const float* wc  = Wc + half * 64;
        float acc = 0.f;
#pragma unroll 16
        for (int o = 0; o < 64; ++o) acc = fmaf(row[o], wc[o], acc);
        acc += __shfl_xor_sync(0xffffffffu, acc, 1);
        if (!half) ws[m] = acc;
    }
    if (t < 128) {
        float p = be2[t] * Wc[t];
#pragma unroll
        for (int s = 16; s > 0; s >>= 1)
            p += __shfl_xor_sync(0xffffffffu, p, s);
        if (l == 0) cp[w] = p;
    }
    __syncthreads();
    if (t == 0) cv[0] = cp[0] + cp[1] + cp[2] + cp[3] + bc[0];
    if (t < 128) { float s = (ws[t] >= 0.f) ? 1.0f : -1.0f; Sd[2 * t] = s; Sd[2 * t + 1] = s; }

    // ---- reduce partials + alpha/beta: thread owns (row = t>>7, o = t&127) ----
    {
        int row = t >> 7;
        int o = t & 127;
        const float SCALE = 0.08838834764831845f;  // 1/sqrt(128)

        float q = bq[o], k = bk[o], v = bv[o];
#pragma unroll
        for (int seg = 0; seg < 4; ++seg) {
            int pb = (seg * 128 + o) * 9 + row;
            q += sm[PH_PQ + pb];
            k += sm[PH_PK + pb];
            v += sm[PH_PV + pb];
        }
        Qd[o * 8 + row] = q * SCALE;
        g_v[(r0 + row) * H + o] = v;

        float wo = ws[o];
        float u  = fmaf(xs2[row * 2], We1[o], xs2[row * 2 + 1] * We1[H + o]);
        float al = 0.5f * wo * (u + be1[o]);
        float be = -0.5f * wo * u;
        Ad[o * 8 + row] = al;
        *(float2*)&g_kbT[o * (2 * NN) + 2 * (r0 + row)] = make_float2(k, be);

        // warp = one row (32 o's): reduce alpha/beta
        float sA = al, sB = be;
#pragma unroll
        for (int s = 16; s > 0; s >>= 1) {
            sA += __shfl_xor_sync(0xffffffffu, sA, s);
            sB += __shfl_xor_sync(0xffffffffu, sB, s);
        }
        if (l == 0) { WP2[w * 2] = sA; WP2[w * 2 + 1] = sB; }
    }
    __syncthreads();
    if (t < 8) {
        int row = t;
        float A = 0.f, B = 0.f;
#pragma unroll
        for (int k2 = 0; k2 < 4; ++k2) {
            A += WP2[(row * 4 + k2) * 2];
            B += WP2[(row * 4 + k2) * 2 + 1];
        }
        ASH[row] = cv[0] + A;
        g_B[r0 + row] = B;
    }

    // ===================== GRID BARRIER ====================================
    __syncthreads();
    if (t == 0) {
        __threadfence();
        unsigned g = bar_gen;
        if (atomicAdd(&bar_cnt, 1) == (unsigned)(gridDim.x - 1)) {
            bar_cnt = 0;
            __threadfence();
            bar_gen = g + 1;
        } else {
            while (bar_gen == g) { __nanosleep(64); }
            __threadfence();
        }
    }
    __syncthreads();

    // ===================== PHASE 2: fused attention ========================
    // Fused score + gate m-loop (thread owns j = t), 8-m double-buffered kb
    u64 acc[4], ga[4];
#pragma unroll
    for (int ip = 0; ip < 4; ++ip) { acc[ip] = 0ull; ga[ip] = 0ull; }
    {
        const float* kbp = g_kbT + 2 * t;
        float2 bufA[4], bufB[4];
#pragma unroll
        for (int mm = 0; mm < 4; ++mm)
            bufA[mm] = *(const float2*)(kbp + mm * (2 * NN));

#pragma unroll 1
        for (int mg = 0; mg < 16; ++mg) {
            int base = mg * 8;
#pragma unroll
            for (int mm = 0; mm < 4; ++mm)
                bufB[mm] = *(const float2*)(kbp + (base + 4 + mm) * (2 * NN));
#pragma unroll
            for (int mm = 0; mm < 4; ++mm) {
                int m = base + mm;
                u64 kd = f2dup(bufA[mm].x);
                u64 bd = f2dup(bufA[mm].y);
                u64 sd = *(const u64*)(Sd + 2 * m);
                ulonglong2 qA = *(const ulonglong2*)(Qd + m * 8);
                ulonglong2 qB = *(const ulonglong2*)(Qd + m * 8 + 4);
                ulonglong2 aA = *(const ulonglong2*)(Ad + m * 8);
                ulonglong2 aB = *(const ulonglong2*)(Ad + m * 8 + 4);
                f2fma(acc[0], qA.x, kd);
                f2fma(acc[1], qA.y, kd);
                f2fma(acc[2], qB.x, kd);
                f2fma(acc[3], qB.y, kd);
                u64 z;
                z = f2add(aA.x, bd) & ABSM; f2fma(ga[0], z, sd);
                z = f2add(aA.y, bd) & ABSM; f2fma(ga[1], z, sd);
                z = f2add(aB.x, bd) & ABSM; f2fma(ga[2], z, sd);
                z = f2add(aB.y, bd) & ABSM; f2fma(ga[3], z, sd);
            }
#pragma unroll
            for (int mm = 0; mm < 4; ++mm)
                bufA[mm] = *(const float2*)(kbp + (base + 8 + mm) * (2 * NN));  // pad rows at tail
#pragma unroll
            for (int mm = 0; mm < 4; ++mm) {
                int m = base + 4 + mm;
                u64 kd = f2dup(bufB[mm].x);
                u64 bd = f2dup(bufB[mm].y);
                u64 sd = *(const u64*)(Sd + 2 * m);
                ulonglong2 qA = *(const ulonglong2*)(Qd + m * 8);
                ulonglong2 qB = *(const ulonglong2*)(Qd + m * 8 + 4);
                ulonglong2 aA = *(const ulonglong2*)(Ad + m * 8);
                ulonglong2 aB = *(const ulonglong2*)(Ad + m * 8 + 4);
                f2fma(acc[0], qA.x, kd);
                f2fma(acc[1], qA.y, kd);
                f2fma(acc[2], qB.x, kd);
                f2fma(acc[3], qB.y, kd);
                u64 z;
                z = f2add(aA.x, bd) & ABSM; f2fma(ga[0], z, sd);
                z = f2add(aA.y, bd) & ABSM; f2fma(ga[1], z, sd);
                z = f2add(aB.x, bd) & ABSM; f2fma(ga[2], z, sd);
                z = f2add(aB.y, bd) & ABSM; f2fma(ga[3], z, sd);
            }
        }
    }
#pragma unroll
    for (int ip = 0; ip < 4; ++ip) {
        float2 f = f2un(acc[ip]);
        P[(2 * ip) * NN + t]     = f.x;
        P[(2 * ip + 1) * NN + t] = f.y;
    }
    __syncthreads();

    // Softmax: 4 warps per row (quarters)
    {
        int row = w >> 2, qt = w & 3;
        float* prow = P + row * NN + qt * 256;
        float mx = -1e30f;
        for (int j = l; j < 256; j += 32) mx = fmaxf(mx, prow[j]);
#pragma unroll
        for (int s = 16; s > 0; s >>= 1)
            mx = fmaxf(mx, __shfl_xor_sync(0xffffffffu, mx, s));
        if (l == 0) SMX[w] = mx;
        __syncthreads();
        float M = fmaxf(fmaxf(SMX[row * 4], SMX[row * 4 + 1]),
                        fmaxf(SMX[row * 4 + 2], SMX[row * 4 + 3]));
        float sum = 0.f;
        for (int j = l; j < 256; j += 32) {
            float e = __expf(prow[j] - M);
            prow[j] = e;
            sum += e;
        }
#pragma unroll
        for (int s = 16; s > 0; s >>= 1)
            sum += __shfl_xor_sync(0xffffffffu, sum, s);
        if (l == 0) SSUM[w] = sum;
        __syncthreads();
        float inv = 1.f / (SSUM[row * 4] + SSUM[row * 4 + 1]
                         + SSUM[row * 4 + 2] + SSUM[row * 4 + 3]);
        for (int j = l; j < 256; j += 32) prow[j] *= inv;
    }
    __syncthreads();

    // Gate combine: delta_x (thread owns j = t)
    {
        float pv[8];
#pragma unroll
        for (int i = 0; i < 8; ++i) pv[i] = P[i * NN + t];
        *(float4*)&P2[t * 8]     = make_float4(pv[0], pv[1], pv[2], pv[3]);
        *(float4*)&P2[t * 8 + 4] = make_float4(pv[4], pv[5], pv[6], pv[7]);
        __syncwarp();

        float Bj = g_B[t];
        float2 xj = *(const float2*)(x + 2 * t);
        float dxv[8], dyv[8];
#pragma unroll
        for (int ip = 0; ip < 4; ++ip) {
            float2 g2 = f2un(ga[ip]);
            int ia = 2 * ip, ib = 2 * ip + 1;
            float G0 = ASH[ia] + Bj + g2.x;
            float G1 = ASH[ib] + Bj + g2.y;
            float pg0 = pv[ia] * G0;
            float pg1 = pv[ib] * G1;
            dxv[ia] = pg0 * (XI[2 * ia]     - xj.x);
            dyv[ia] = pg0 * (XI[2 * ia + 1] - xj.y);
            dxv[ib] = pg1 * (XI[2 * ib]     - xj.x);
            dyv[ib] = pg1 * (XI[2 * ib + 1] - xj.y);
        }
#pragma unroll
        for (int s = 16; s > 0; s >>= 1) {
#pragma unroll
            for (int i = 0; i < 8; ++i) {
                dxv[i] += __shfl_xor_sync(0xffffffffu, dxv[i], s);
                dyv[i] += __shfl_xor_sync(0xffffffffu, dyv[i], s);
            }
        }
        if (l == 0) {
#pragma unroll
            for (int i = 0; i < 8; ++i) {
                DXS[w * 16 + 2 * i]     = dxv[i];
                DXS[w * 16 + 2 * i + 1] = dyv[i];
            }
        }
    }

    // AV: warp owns 32 j's, lane owns 4 cols
    {
        u64 av[8][2];
#pragma unroll
        for (int i = 0; i < 8; ++i) { av[i][0] = 0ull; av[i][1] = 0ull; }
        int c0 = l << 2;
        int jbase = w << 5;
#pragma unroll 2
        for (int jj = 0; jj < 32; ++jj) {
            int j = jbase + jj;
            ulonglong2 v2 = *(const ulonglong2*)(g_v + j * H + c0);
            float4 pa = *(const float4*)&P2[j * 8];
            float4 pb = *(const float4*)&P2[j * 8 + 4];
            f2fma(av[0][0], f2dup(pa.x), v2.x); f2fma(av[0][1], f2dup(pa.x), v2.y);
            f2fma(av[1][0], f2dup(pa.y), v2.x); f2fma(av[1][1], f2dup(pa.y), v2.y);
            f2fma(av[2][0], f2dup(pa.z), v2.x); f2fma(av[2][1], f2dup(pa.z), v2.y);
            f2fma(av[3][0], f2dup(pa.w), v2.x); f2fma(av[3][1], f2dup(pa.w), v2.y);
            f2fma(av[4][0], f2dup(pb.x), v2.x); f2fma(av[4][1], f2dup(pb.x), v2.y);
            f2fma(av[5][0], f2dup(pb.y), v2.x); f2fma(av[5][1], f2dup(pb.y), v2.y);
            f2fma(av[6][0], f2dup(pb.z), v2.x); f2fma(av[6][1], f2dup(pb.z), v2.y);
            f2fma(av[7][0], f2dup(pb.w), v2.x); f2fma(av[7][1], f2dup(pb.w), v2.y);
        }
#pragma unroll
        for (int i = 0; i < 8; ++i) {
            float2 a = f2un(av[i][0]);
            float2 b = f2un(av[i][1]);
            *(float4*)&AVP[(w * 8 + i) * 128 + c0] = make_float4(a.x, a.y, b.x, b.y);
        }
    }
    __syncthreads();

    // Final reduce + epilogue
    {
        int i = t >> 7, c = t & 127;
        float s = 0.f;
#pragma unroll
        for (int w2 = 0; w2 < 32; ++w2)
            s += AVP[(w2 * 8 + i) * 128 + c];
        out_h[(i0 + i) * H + c] = h[(i0 + i) * H + c] + s;
    }
    if (t < 16) {
        int i = t >> 1, d = t & 1;
        float s = 0.f;
#pragma unroll
        for (int w2 = 0; w2 < 32; ++w2) s += DXS[w2 * 16 + 2 * i + d];
        out_x[(i0 + i) * 2 + d] = x[(i0 + i) * 2 + d] + s;
    }
}

// ---------------------------------------------------------------------------
extern "C" void kernel_launch(void* const* d_in, const int* in_sizes, int n_in,
                              void* d_out, int out_size)
{
    const float* h   = (const float*)d_in[0];
    const float* x   = (const float*)d_in[1];
    const float* Wq  = (const float*)d_in[3];
    const float* bq  = (const float*)d_in[4];
    const float* Wk  = (const float*)d_in[5];
    const float* bk  = (const float*)d_in[6];
    const float* Wv  = (const float*)d_in[7];
    const float* bv  = (const float*)d_in[8];
    const float* We1 = (const float*)d_in[9];
    const float* be1 = (const float*)d_in[10];
    const float* We2 = (const float*)d_in[11];
    const float* be2 = (const float*)d_in[12];
    const float* Wc  = (const float*)d_in[13];
    const float* bc  = (const float*)d_in[14];

    float* out   = (float*)d_out;
    float* out_h = out;
    float* out_x = out + NN * H;

    size_t smem_bytes = (size_t)SMEM_FLOATS * sizeof(float);
    cudaFuncSetAttribute(fused_kernel,
                         cudaFuncAttributeMaxDynamicSharedMemorySize,
                         (int)smem_bytes);

    fused_kernel<<<NBLOCKS, THREADS, smem_bytes>>>(
        h, x, Wq, bq, Wk, bk, Wv, bv, We1, be1, We2, be2, Wc, bc,
        out_h, out_x);
}